// round 7
// baseline (speedup 1.0000x reference)
#include <cuda_runtime.h>
#include <cuda_bf16.h>

#define HID 256
#define GAMMA_F 12.0f
#define BATCH 8
#define NBLOCKS 444      // 3 CTA/SM x 148 SMs: one resident wave (barrier-safe)
#define NTHREADS 256

__device__ float g_scores[BATCH * 100000];  // S[e*8+b], 3.2MB (L2-resident)

// Replay-safe grid barrier: generation counter only increases across replays.
__device__ unsigned g_count = 0;
__device__ unsigned g_gen = 0;

__device__ __forceinline__ void grid_barrier(int nblocks) {
    __syncthreads();
    if (threadIdx.x == 0) {
        const unsigned gen = *((volatile unsigned*)&g_gen);
        __threadfence();                       // release phase-1 writes
        const unsigned arr = atomicAdd(&g_count, 1);
        if (arr == (unsigned)nblocks - 1) {
            g_count = 0;                       // no one reads it again this episode
            __threadfence();
            atomicAdd(&g_gen, 1);              // release
        } else {
            while (*((volatile unsigned*)&g_gen) == gen) { }
        }
        __threadfence();                       // acquire
    }
    __syncthreads();
}

__global__ void __launch_bounds__(NTHREADS, 3)
kge_fused_kernel(const float* __restrict__ ent,
                 const float* __restrict__ rel,
                 const int*   __restrict__ pos,
                 const int*   __restrict__ neg,
                 float*       __restrict__ out,
                 int ne, int nneg)
{
    const int lane = threadIdx.x & 31;
    const int warp = threadIdx.x >> 5;
    float* const scores = g_scores;

    // ---------------- Phase 1 ---------------------------------------------
    // Warp pair (warp>>1) shares a row chunk; parity picks batches 0-3 / 4-7.
    // Lane owns dims [lane*8, lane*8+8). hrs = 2*(head+rel): 32 regs.
    const int parity = warp & 1;
    const int bbase  = parity * 4;

    float hrs[4][8];
#pragma unroll
    for (int bb = 0; bb < 4; bb++) {
        const int b = bbase + bb;
        const int hidx = pos[b * 3 + 0];
        const int ridx = pos[b * 3 + 1];
        const float4* h4 = reinterpret_cast<const float4*>(ent + (size_t)hidx * HID);
        const float4* r4 = reinterpret_cast<const float4*>(rel + (size_t)ridx * HID);
        float4 h0 = h4[lane * 2], h1 = h4[lane * 2 + 1];
        float4 r0 = r4[lane * 2], r1 = r4[lane * 2 + 1];
        hrs[bb][0] = 2.0f * (h0.x + r0.x);  hrs[bb][1] = 2.0f * (h0.y + r0.y);
        hrs[bb][2] = 2.0f * (h0.z + r0.z);  hrs[bb][3] = 2.0f * (h0.w + r0.w);
        hrs[bb][4] = 2.0f * (h1.x + r1.x);  hrs[bb][5] = 2.0f * (h1.y + r1.y);
        hrs[bb][6] = 2.0f * (h1.z + r1.z);  hrs[bb][7] = 2.0f * (h1.w + r1.w);
    }

    const bool hi16 = (lane & 16) != 0;
    const bool hi8  = (lane & 8)  != 0;

    // Contiguous row chunk per warp PAIR.
    const int gp = blockIdx.x * (NTHREADS >> 6) + (warp >> 1);
    const int P  = gridDim.x * (NTHREADS >> 6);
    const int per   = ne / P;
    const int rem   = ne % P;
    const int start = gp * per + (gp < rem ? gp : rem);
    const int end   = start + per + (gp < rem ? 1 : 0);

    float e[8], p[8];
    if (start < end) {
        const float4* er = reinterpret_cast<const float4*>(ent + (size_t)start * HID);
        float4 x = er[lane * 2], y = er[lane * 2 + 1];
        e[0]=x.x; e[1]=x.y; e[2]=x.z; e[3]=x.w;
        e[4]=y.x; e[5]=y.y; e[6]=y.z; e[7]=y.w;
    }

    for (int row = start; row < end; row++) {
        if (row + 1 < end) {  // prefetch next row
            const float4* pr = reinterpret_cast<const float4*>(ent + (size_t)(row + 1) * HID);
            float4 x = pr[lane * 2], y = pr[lane * 2 + 1];
            p[0]=x.x; p[1]=x.y; p[2]=x.z; p[3]=x.w;
            p[4]=y.x; p[5]=y.y; p[6]=y.z; p[7]=y.w;
        }

        float v[4];
#pragma unroll
        for (int bb = 0; bb < 4; bb++) {
            float acc = 0.0f;
#pragma unroll
            for (int j = 0; j < 8; j++) {
                const float d2 = __fmaf_rn(e[j], -2.0f, hrs[bb][j]);  // FFMA-imm
                acc += fabsf(d2);                                     // FADD |src|
            }
            v[bb] = acc;   // = 2 * partial L1 distance over lane's 8 dims
        }

        // Fold 4 -> 1: after these two stages, lane's value is for batch
        // bbase + ((lane>>3)&3), summed over dims of lanes {lane^0,8,16,24}.
        {
            const float s0 = hi16 ? v[0] : v[2];
            const float s1 = hi16 ? v[1] : v[3];
            const float r0 = __shfl_xor_sync(0xFFFFFFFFu, s0, 16);
            const float r1 = __shfl_xor_sync(0xFFFFFFFFu, s1, 16);
            v[0] = (hi16 ? v[2] : v[0]) + r0;
            v[1] = (hi16 ? v[3] : v[1]) + r1;
        }
        {
            const float s = hi8 ? v[0] : v[1];
            const float r = __shfl_xor_sync(0xFFFFFFFFu, s, 8);
            v[0] = (hi8 ? v[1] : v[0]) + r;
        }
        // Butterfly over remaining 8-lane group (bits 2,1,0) -> full 256 dims.
        v[0] += __shfl_xor_sync(0xFFFFFFFFu, v[0], 4);
        v[0] += __shfl_xor_sync(0xFFFFFFFFu, v[0], 2);
        v[0] += __shfl_xor_sync(0xFFFFFFFFu, v[0], 1);

        if ((lane & 7) == 0)   // score = gamma - 0.5 * (2*dist)   (FFMA-imm)
            scores[(size_t)row * BATCH + bbase + ((lane >> 3) & 3)] =
                __fmaf_rn(v[0], -0.5f, GAMMA_F);

#pragma unroll
        for (int j = 0; j < 8; j++) e[j] = p[j];
    }

    // ---------------- Barrier ----------------------------------------------
    grid_barrier(gridDim.x);

    // ---------------- Phase 2: out[b][n] = scores[neg[b][n]*8 + b] ---------
    const int n4   = nneg >> 2;
    const int jobs = BATCH * n4;
    const int nthr = gridDim.x * NTHREADS;
    const int gtid = blockIdx.x * NTHREADS + threadIdx.x;

    for (int j = gtid; j < jobs; j += nthr) {
        const int b = j / n4;
        const int t = j - b * n4;
        const int4 idx = reinterpret_cast<const int4*>(neg + (size_t)b * nneg)[t];
        float4 r;
        r.x = scores[(size_t)idx.x * BATCH + b];
        r.y = scores[(size_t)idx.y * BATCH + b];
        r.z = scores[(size_t)idx.z * BATCH + b];
        r.w = scores[(size_t)idx.w * BATCH + b];
        reinterpret_cast<float4*>(out + (size_t)b * nneg)[t] = r;
    }
    const int tail = nneg - n4 * 4;
    for (int j = gtid; j < BATCH * tail; j += nthr) {
        const int b = j / tail;
        const int n = n4 * 4 + (j - b * tail);
        out[(size_t)b * nneg + n] = scores[(size_t)neg[(size_t)b * nneg + n] * BATCH + b];
    }
}

extern "C" void kernel_launch(void* const* d_in, const int* in_sizes, int n_in,
                              void* d_out, int out_size)
{
    const float* ent = (const float*)d_in[0];  // [NE, 256] f32
    const float* rel = (const float*)d_in[1];  // [NR, 256] f32
    const int*   pos = (const int*)d_in[2];    // [B, 3] i32
    const int*   neg = (const int*)d_in[3];    // [B, N] i32
    float*       out = (float*)d_out;          // [B, N] f32

    const int batch = in_sizes[2] / 3;         // 8
    const int nneg  = in_sizes[3] / batch;     // 100000
    const int ne    = in_sizes[0] / HID;       // 100000
    (void)batch;

    kge_fused_kernel<<<NBLOCKS, NTHREADS>>>(ent, rel, pos, neg, out, ne, nneg);
}